// round 15
// baseline (speedup 1.0000x reference)
#include <cuda_runtime.h>
#include <math_constants.h>

// Fixed shapes
#define BB   8
#define NN   8192
#define SS   2048
#define DD   256
#define QB   128            // queries per block
#define QPT  2              // queries per thread (register-resident)
#define QGRP (QB / QPT)     // 64 query groups
#define NPART 4             // S split 4 ways
#define TPB  (QGRP * NPART) // 256 threads
#define SPT  (SS / NPART)   // 512 points per thread
#define EPSF 1e-8f

// Insert (t,s) into ascending top-3 (D0<=D1<=D2). Strict '<' keeps earlier
// (lower-index) entries on ties, matching top_k's first-occurrence rule.
#define INS(t, s, D0, D1, D2, I0, I1, I2)                                \
    if ((t) < D2) {                                                      \
        if ((t) < D1) {                                                  \
            D2 = D1; I2 = I1;                                            \
            if ((t) < D0) { D1 = D0; I1 = I0; D0 = (t); I0 = (s); }      \
            else          { D1 = (t); I1 = (s); }                        \
        } else { D2 = (t); I2 = (s); }                                   \
    }

struct MergeScratch {
    float d[NPART - 1][QB][3];
    int   i[NPART - 1][QB][3];
};

__global__ __launch_bounds__(TPB)
void fp_interp_kernel(const float* __restrict__ xyz1,     // [B,3,N]
                      const float* __restrict__ xyz2,     // [B,3,S]
                      const float* __restrict__ points2,  // [B,S,D]
                      float* __restrict__ out)            // [B,N,D]
{
    // sxyz is dead after the scan; merge scratch overlays it.
    __shared__ union SU {
        float4 sxyz[SS];           // 32 KB: (x, y, z, |p|^2)
        MergeScratch mrg;          // 9 KB, used after scan
    } U;
    __shared__ float swgt[QB][3];
    __shared__ int   sidx[QB][3];

    const int tile = blockIdx.x;   // 0..511 (64 tiles per batch)
    const int b    = tile >> 6;
    const int n0   = (tile & 63) * QB;
    const int tid  = threadIdx.x;

    // --- stage xyz2[b] into shared with precomputed |p|^2 ---
    const float* x2b = xyz2 + (size_t)b * 3 * SS;
    #pragma unroll
    for (int s = tid; s < SS; s += TPB) {
        const float x = x2b[s], y = x2b[SS + s], z = x2b[2 * SS + s];
        U.sxyz[s] = make_float4(x, y, z, fmaf(x, x, fmaf(y, y, z * z)));
    }
    __syncthreads();

    // --- phase 1: each thread scans SPT points for TWO register-resident
    //     queries; one LDS stream feeds both.  t = |p|^2 - 2 q.p  (same
    //     ordering as the true squared distance d = t + |q|^2). ---
    const int qg   = tid & (QGRP - 1);   // 0..63
    const int part = tid >> 6;           // 0..3 (uniform per warp pair)
    const int qa   = qg;                 // query 0 of this thread
    const int qb_  = qg + QGRP;          // query 1 of this thread
    const float* x1b = xyz1 + (size_t)b * 3 * NN;

    const float qxa = x1b[n0 + qa], qya = x1b[NN + n0 + qa], qza = x1b[2 * NN + n0 + qa];
    const float qxb = x1b[n0 + qb_], qyb = x1b[NN + n0 + qb_], qzb = x1b[2 * NN + n0 + qb_];
    const float axa = -2.0f * qxa, aya = -2.0f * qya, aza = -2.0f * qza;
    const float axb = -2.0f * qxb, ayb = -2.0f * qyb, azb = -2.0f * qzb;
    const float qqa = fmaf(qxa, qxa, fmaf(qya, qya, qza * qza));
    const float qqb = fmaf(qxb, qxb, fmaf(qyb, qyb, qzb * qzb));

    float a0 = CUDART_MAX_NORMAL_F, a1 = CUDART_MAX_NORMAL_F, a2 = CUDART_MAX_NORMAL_F;
    int   ai0 = 0, ai1 = 0, ai2 = 0;
    float b0 = CUDART_MAX_NORMAL_F, b1 = CUDART_MAX_NORMAL_F, b2 = CUDART_MAX_NORMAL_F;
    int   bi0 = 0, bi1 = 0, bi2 = 0;

    const int sbeg = part * SPT;
    #pragma unroll 2
    for (int s = sbeg; s < sbeg + SPT; s += 4) {
        const float4 p0 = U.sxyz[s];
        const float4 p1 = U.sxyz[s + 1];
        const float4 p2 = U.sxyz[s + 2];
        const float4 p3 = U.sxyz[s + 3];
        // query A
        const float ta0 = fmaf(p0.x, axa, fmaf(p0.y, aya, fmaf(p0.z, aza, p0.w)));
        const float ta1 = fmaf(p1.x, axa, fmaf(p1.y, aya, fmaf(p1.z, aza, p1.w)));
        const float ta2 = fmaf(p2.x, axa, fmaf(p2.y, aya, fmaf(p2.z, aza, p2.w)));
        const float ta3 = fmaf(p3.x, axa, fmaf(p3.y, aya, fmaf(p3.z, aza, p3.w)));
        // query B
        const float tb0 = fmaf(p0.x, axb, fmaf(p0.y, ayb, fmaf(p0.z, azb, p0.w)));
        const float tb1 = fmaf(p1.x, axb, fmaf(p1.y, ayb, fmaf(p1.z, azb, p1.w)));
        const float tb2 = fmaf(p2.x, axb, fmaf(p2.y, ayb, fmaf(p2.z, azb, p2.w)));
        const float tb3 = fmaf(p3.x, axb, fmaf(p3.y, ayb, fmaf(p3.z, azb, p3.w)));
        const float ma = fminf(fminf(ta0, ta1), fminf(ta2, ta3));
        const float mb = fminf(fminf(tb0, tb1), fminf(tb2, tb3));
        if (ma < a2) {                 // rare
            INS(ta0, s,     a0, a1, a2, ai0, ai1, ai2)
            INS(ta1, s + 1, a0, a1, a2, ai0, ai1, ai2)
            INS(ta2, s + 2, a0, a1, a2, ai0, ai1, ai2)
            INS(ta3, s + 3, a0, a1, a2, ai0, ai1, ai2)
        }
        if (mb < b2) {                 // rare
            INS(tb0, s,     b0, b1, b2, bi0, bi1, bi2)
            INS(tb1, s + 1, b0, b1, b2, bi0, bi1, bi2)
            INS(tb2, s + 2, b0, b1, b2, bi0, bi1, bi2)
            INS(tb3, s + 3, b0, b1, b2, bi0, bi1, bi2)
        }
    }

    // --- merge the 4 partial triples per query (parts 1..3 publish; part 0 merges) ---
    __syncthreads();                 // sxyz reads done; safe to overlay
    if (part) {
        U.mrg.d[part - 1][qa][0] = a0; U.mrg.d[part - 1][qa][1] = a1; U.mrg.d[part - 1][qa][2] = a2;
        U.mrg.i[part - 1][qa][0] = ai0; U.mrg.i[part - 1][qa][1] = ai1; U.mrg.i[part - 1][qa][2] = ai2;
        U.mrg.d[part - 1][qb_][0] = b0; U.mrg.d[part - 1][qb_][1] = b1; U.mrg.d[part - 1][qb_][2] = b2;
        U.mrg.i[part - 1][qb_][0] = bi0; U.mrg.i[part - 1][qb_][1] = bi1; U.mrg.i[part - 1][qb_][2] = bi2;
    }
    __syncthreads();
    if (!part) {
        #pragma unroll
        for (int p = 0; p < NPART - 1; ++p) {
            #pragma unroll
            for (int k = 0; k < 3; ++k) {
                const float ta = U.mrg.d[p][qa][k];
                const int   sa = U.mrg.i[p][qa][k];
                INS(ta, sa, a0, a1, a2, ai0, ai1, ai2)
                const float tb = U.mrg.d[p][qb_][k];
                const int   sb = U.mrg.i[p][qb_][k];
                INS(tb, sb, b0, b1, b2, bi0, bi1, bi2)
            }
        }
        // true squared distances and inverse-distance weights (both queries)
        {
            const float r0 = 1.0f / ((a0 + qqa) + EPSF);
            const float r1 = 1.0f / ((a1 + qqa) + EPSF);
            const float r2 = 1.0f / ((a2 + qqa) + EPSF);
            const float inv = 1.0f / (r0 + r1 + r2);
            sidx[qa][0] = ai0; sidx[qa][1] = ai1; sidx[qa][2] = ai2;
            swgt[qa][0] = r0 * inv; swgt[qa][1] = r1 * inv; swgt[qa][2] = r2 * inv;
        }
        {
            const float r0 = 1.0f / ((b0 + qqb) + EPSF);
            const float r1 = 1.0f / ((b1 + qqb) + EPSF);
            const float r2 = 1.0f / ((b2 + qqb) + EPSF);
            const float inv = 1.0f / (r0 + r1 + r2);
            sidx[qb_][0] = bi0; sidx[qb_][1] = bi1; sidx[qb_][2] = bi2;
            swgt[qb_][0] = r0 * inv; swgt[qb_][1] = r1 * inv; swgt[qb_][2] = r2 * inv;
        }
    }
    __syncthreads();

    // --- phase 2: cooperative gather + weighted sum, coalesced float4 ---
    const int warp = tid >> 5;      // 0..7
    const int lane = tid & 31;
    const float4* p2f = (const float4*)(points2 + (size_t)b * SS * DD); // rows of 64 float4
    float4* ob = (float4*)(out + ((size_t)b * NN + n0) * DD);

    #pragma unroll
    for (int qi = warp; qi < QB; qi += TPB / 32) {
        const int j0 = sidx[qi][0] * (DD / 4);
        const int j1 = sidx[qi][1] * (DD / 4);
        const int j2 = sidx[qi][2] * (DD / 4);
        const float w0 = swgt[qi][0];
        const float w1 = swgt[qi][1];
        const float w2 = swgt[qi][2];
        float4* oq = ob + (size_t)qi * (DD / 4);
        #pragma unroll
        for (int j = lane; j < DD / 4; j += 32) {
            const float4 a = p2f[j0 + j];
            const float4 c = p2f[j1 + j];
            const float4 e = p2f[j2 + j];
            float4 r;
            r.x = w0 * a.x + w1 * c.x + w2 * e.x;
            r.y = w0 * a.y + w1 * c.y + w2 * e.y;
            r.z = w0 * a.z + w1 * c.z + w2 * e.z;
            r.w = w0 * a.w + w1 * c.w + w2 * e.w;
            oq[j] = r;
        }
    }
}

extern "C" void kernel_launch(void* const* d_in, const int* in_sizes, int n_in,
                              void* d_out, int out_size)
{
    // inputs: xyz1 [B,3,N], xyz2 [B,3,S], points1 [B,D,N] (unused), points2 [B,S,D]
    const float* xyz1    = (const float*)d_in[0];
    const float* xyz2    = (const float*)d_in[1];
    const float* points2 = (const float*)d_in[3];
    float* out = (float*)d_out;

    const int blocks = BB * (NN / QB);   // 8 * 64 = 512
    fp_interp_kernel<<<blocks, TPB>>>(xyz1, xyz2, points2, out);
}

// round 16
// speedup vs baseline: 1.0606x; 1.0606x over previous
#include <cuda_runtime.h>
#include <math_constants.h>

// Fixed shapes
#define BB   8
#define NN   8192
#define SS   2048
#define DD   256
#define QB   128            // queries per block
#define QPT  2              // queries per thread (register-resident)
#define QGRP (QB / QPT)     // 64 query groups
#define NPART 4             // S split 4 ways
#define TPB  (QGRP * NPART) // 256 threads
#define SPT  (SS / NPART)   // 512 points per thread
#define EPSF 1e-8f

// Insert (t,s) into ascending top-3 (D0<=D1<=D2). Strict '<' keeps earlier
// (lower-index) entries on ties, matching top_k's first-occurrence rule.
#define INS(t, s, D0, D1, D2, I0, I1, I2)                                \
    if ((t) < D2) {                                                      \
        if ((t) < D1) {                                                  \
            D2 = D1; I2 = I1;                                            \
            if ((t) < D0) { D1 = D0; I1 = I0; D0 = (t); I0 = (s); }      \
            else          { D1 = (t); I1 = (s); }                        \
        } else { D2 = (t); I2 = (s); }                                   \
    }

struct MergeScratch {
    float d[NPART - 1][QB][3];
    int   i[NPART - 1][QB][3];
};

__global__ __launch_bounds__(TPB)
void fp_interp_kernel(const float* __restrict__ xyz1,     // [B,3,N]
                      const float* __restrict__ xyz2,     // [B,3,S]
                      const float* __restrict__ points2,  // [B,S,D]
                      float* __restrict__ out)            // [B,N,D]
{
    // sxyz is dead after the scan; merge scratch overlays it.
    __shared__ union SU {
        float4 sxyz[SS];           // 32 KB: (x, y, z, |p|^2)
        MergeScratch mrg;          // 9 KB, used after scan
    } U;
    __shared__ float swgt[QB][3];
    __shared__ int   sidx[QB][3];

    const int tile = blockIdx.x;   // 0..511 (64 tiles per batch)
    const int b    = tile >> 6;
    const int n0   = (tile & 63) * QB;
    const int tid  = threadIdx.x;

    // --- stage xyz2[b] into shared with precomputed |p|^2 ---
    const float* x2b = xyz2 + (size_t)b * 3 * SS;
    #pragma unroll
    for (int s = tid; s < SS; s += TPB) {
        const float x = x2b[s], y = x2b[SS + s], z = x2b[2 * SS + s];
        U.sxyz[s] = make_float4(x, y, z, fmaf(x, x, fmaf(y, y, z * z)));
    }
    __syncthreads();

    // --- phase 1: each thread scans SPT points for TWO register-resident
    //     queries; one LDS stream feeds both.  t = |p|^2 - 2 q.p  (same
    //     ordering as the true squared distance d = t + |q|^2). ---
    const int qg   = tid & (QGRP - 1);   // 0..63
    const int part = tid >> 6;           // 0..3 (uniform per warp pair)
    const int qa   = qg;                 // query 0 of this thread
    const int qb_  = qg + QGRP;          // query 1 of this thread
    const float* x1b = xyz1 + (size_t)b * 3 * NN;

    const float qxa = x1b[n0 + qa], qya = x1b[NN + n0 + qa], qza = x1b[2 * NN + n0 + qa];
    const float qxb = x1b[n0 + qb_], qyb = x1b[NN + n0 + qb_], qzb = x1b[2 * NN + n0 + qb_];
    const float axa = -2.0f * qxa, aya = -2.0f * qya, aza = -2.0f * qza;
    const float axb = -2.0f * qxb, ayb = -2.0f * qyb, azb = -2.0f * qzb;
    const float qqa = fmaf(qxa, qxa, fmaf(qya, qya, qza * qza));
    const float qqb = fmaf(qxb, qxb, fmaf(qyb, qyb, qzb * qzb));

    float a0 = CUDART_MAX_NORMAL_F, a1 = CUDART_MAX_NORMAL_F, a2 = CUDART_MAX_NORMAL_F;
    int   ai0 = 0, ai1 = 0, ai2 = 0;
    float b0 = CUDART_MAX_NORMAL_F, b1 = CUDART_MAX_NORMAL_F, b2 = CUDART_MAX_NORMAL_F;
    int   bi0 = 0, bi1 = 0, bi2 = 0;

    const int sbeg = part * SPT;
    #pragma unroll 2
    for (int s = sbeg; s < sbeg + SPT; s += 4) {
        const float4 p0 = U.sxyz[s];
        const float4 p1 = U.sxyz[s + 1];
        const float4 p2 = U.sxyz[s + 2];
        const float4 p3 = U.sxyz[s + 3];
        // query A
        const float ta0 = fmaf(p0.x, axa, fmaf(p0.y, aya, fmaf(p0.z, aza, p0.w)));
        const float ta1 = fmaf(p1.x, axa, fmaf(p1.y, aya, fmaf(p1.z, aza, p1.w)));
        const float ta2 = fmaf(p2.x, axa, fmaf(p2.y, aya, fmaf(p2.z, aza, p2.w)));
        const float ta3 = fmaf(p3.x, axa, fmaf(p3.y, aya, fmaf(p3.z, aza, p3.w)));
        // query B
        const float tb0 = fmaf(p0.x, axb, fmaf(p0.y, ayb, fmaf(p0.z, azb, p0.w)));
        const float tb1 = fmaf(p1.x, axb, fmaf(p1.y, ayb, fmaf(p1.z, azb, p1.w)));
        const float tb2 = fmaf(p2.x, axb, fmaf(p2.y, ayb, fmaf(p2.z, azb, p2.w)));
        const float tb3 = fmaf(p3.x, axb, fmaf(p3.y, ayb, fmaf(p3.z, azb, p3.w)));
        const float ma = fminf(fminf(ta0, ta1), fminf(ta2, ta3));
        const float mb = fminf(fminf(tb0, tb1), fminf(tb2, tb3));
        if (ma < a2) {                 // rare
            INS(ta0, s,     a0, a1, a2, ai0, ai1, ai2)
            INS(ta1, s + 1, a0, a1, a2, ai0, ai1, ai2)
            INS(ta2, s + 2, a0, a1, a2, ai0, ai1, ai2)
            INS(ta3, s + 3, a0, a1, a2, ai0, ai1, ai2)
        }
        if (mb < b2) {                 // rare
            INS(tb0, s,     b0, b1, b2, bi0, bi1, bi2)
            INS(tb1, s + 1, b0, b1, b2, bi0, bi1, bi2)
            INS(tb2, s + 2, b0, b1, b2, bi0, bi1, bi2)
            INS(tb3, s + 3, b0, b1, b2, bi0, bi1, bi2)
        }
    }

    // --- merge the 4 partial triples per query (parts 1..3 publish; part 0 merges) ---
    __syncthreads();                 // sxyz reads done; safe to overlay
    if (part) {
        U.mrg.d[part - 1][qa][0] = a0; U.mrg.d[part - 1][qa][1] = a1; U.mrg.d[part - 1][qa][2] = a2;
        U.mrg.i[part - 1][qa][0] = ai0; U.mrg.i[part - 1][qa][1] = ai1; U.mrg.i[part - 1][qa][2] = ai2;
        U.mrg.d[part - 1][qb_][0] = b0; U.mrg.d[part - 1][qb_][1] = b1; U.mrg.d[part - 1][qb_][2] = b2;
        U.mrg.i[part - 1][qb_][0] = bi0; U.mrg.i[part - 1][qb_][1] = bi1; U.mrg.i[part - 1][qb_][2] = bi2;
    }
    __syncthreads();
    if (!part) {
        #pragma unroll
        for (int p = 0; p < NPART - 1; ++p) {
            #pragma unroll
            for (int k = 0; k < 3; ++k) {
                const float ta = U.mrg.d[p][qa][k];
                const int   sa = U.mrg.i[p][qa][k];
                INS(ta, sa, a0, a1, a2, ai0, ai1, ai2)
                const float tb = U.mrg.d[p][qb_][k];
                const int   sb = U.mrg.i[p][qb_][k];
                INS(tb, sb, b0, b1, b2, bi0, bi1, bi2)
            }
        }
        // true squared distances and inverse-distance weights (both queries)
        {
            const float r0 = 1.0f / ((a0 + qqa) + EPSF);
            const float r1 = 1.0f / ((a1 + qqa) + EPSF);
            const float r2 = 1.0f / ((a2 + qqa) + EPSF);
            const float inv = 1.0f / (r0 + r1 + r2);
            sidx[qa][0] = ai0; sidx[qa][1] = ai1; sidx[qa][2] = ai2;
            swgt[qa][0] = r0 * inv; swgt[qa][1] = r1 * inv; swgt[qa][2] = r2 * inv;
        }
        {
            const float r0 = 1.0f / ((b0 + qqb) + EPSF);
            const float r1 = 1.0f / ((b1 + qqb) + EPSF);
            const float r2 = 1.0f / ((b2 + qqb) + EPSF);
            const float inv = 1.0f / (r0 + r1 + r2);
            sidx[qb_][0] = bi0; sidx[qb_][1] = bi1; sidx[qb_][2] = bi2;
            swgt[qb_][0] = r0 * inv; swgt[qb_][1] = r1 * inv; swgt[qb_][2] = r2 * inv;
        }
    }
    __syncthreads();

    // --- phase 2: cooperative gather + weighted sum, coalesced float4 ---
    const int warp = tid >> 5;      // 0..7
    const int lane = tid & 31;
    const float4* p2f = (const float4*)(points2 + (size_t)b * SS * DD); // rows of 64 float4
    float4* ob = (float4*)(out + ((size_t)b * NN + n0) * DD);

    #pragma unroll
    for (int qi = warp; qi < QB; qi += TPB / 32) {
        const int j0 = sidx[qi][0] * (DD / 4);
        const int j1 = sidx[qi][1] * (DD / 4);
        const int j2 = sidx[qi][2] * (DD / 4);
        const float w0 = swgt[qi][0];
        const float w1 = swgt[qi][1];
        const float w2 = swgt[qi][2];
        float4* oq = ob + (size_t)qi * (DD / 4);
        #pragma unroll
        for (int j = lane; j < DD / 4; j += 32) {
            const float4 a = p2f[j0 + j];
            const float4 c = p2f[j1 + j];
            const float4 e = p2f[j2 + j];
            float4 r;
            r.x = w0 * a.x + w1 * c.x + w2 * e.x;
            r.y = w0 * a.y + w1 * c.y + w2 * e.y;
            r.z = w0 * a.z + w1 * c.z + w2 * e.z;
            r.w = w0 * a.w + w1 * c.w + w2 * e.w;
            oq[j] = r;
        }
    }
}

extern "C" void kernel_launch(void* const* d_in, const int* in_sizes, int n_in,
                              void* d_out, int out_size)
{
    // inputs: xyz1 [B,3,N], xyz2 [B,3,S], points1 [B,D,N] (unused), points2 [B,S,D]
    const float* xyz1    = (const float*)d_in[0];
    const float* xyz2    = (const float*)d_in[1];
    const float* points2 = (const float*)d_in[3];
    float* out = (float*)d_out;

    const int blocks = BB * (NN / QB);   // 8 * 64 = 512
    fp_interp_kernel<<<blocks, TPB>>>(xyz1, xyz2, points2, out);
}

// round 17
// speedup vs baseline: 1.6197x; 1.5271x over previous
#include <cuda_runtime.h>
#include <math_constants.h>

// Fixed shapes
#define BB   8
#define NN   8192
#define SS   2048
#define DD   256
#define QB   128            // queries per block
#define NPART 2             // S split 2 ways
#define TPB  (QB * NPART)   // 256 threads
#define SPT  (SS / NPART)   // 1024 points per thread
#define GSZ  8              // candidate-group size
#define EPSF 1e-8f

// Branchless insert of (m,id) into ascending triple (D0<=D1<=D2).
// Strict '<' keeps earlier entries on ties.
#define BINS(m, id, D0, D1, D2, I0, I1, I2) do {                         \
    const float _m = (m); const int _id = (id);                          \
    const bool _l2 = _m < (D2);                                          \
    const bool _l1 = _m < (D1);                                          \
    const bool _l0 = _m < (D0);                                          \
    const float _n2 = _l1 ? (D1) : (_l2 ? _m : (D2));                    \
    const int   _j2 = _l1 ? (I1) : (_l2 ? _id : (I2));                   \
    const float _n1 = _l0 ? (D0) : (_l1 ? _m : (D1));                    \
    const int   _j1 = _l0 ? (I0) : (_l1 ? _id : (I1));                   \
    const float _n0 = _l0 ? _m : (D0);                                   \
    const int   _j0 = _l0 ? _id : (I0);                                  \
    D0 = _n0; D1 = _n1; D2 = _n2; I0 = _j0; I1 = _j1; I2 = _j2;          \
} while (0)

// Cold-path exact insert (branchy is fine off the hot loop).
#define INS(t, s, D0, D1, D2, I0, I1, I2)                                \
    if ((t) < D2) {                                                      \
        if ((t) < D1) {                                                  \
            D2 = D1; I2 = I1;                                            \
            if ((t) < D0) { D1 = D0; I1 = I0; D0 = (t); I0 = (s); }      \
            else          { D1 = (t); I1 = (s); }                        \
        } else { D2 = (t); I2 = (s); }                                   \
    }

__global__ __launch_bounds__(TPB)
void fp_interp_kernel(const float* __restrict__ xyz1,     // [B,3,N]
                      const float* __restrict__ xyz2,     // [B,3,S]
                      const float* __restrict__ points2,  // [B,S,D]
                      float* __restrict__ out)            // [B,N,D]
{
    __shared__ float4 sxyz[SS];                 // 32 KB: (x, y, z, |p|^2)
    __shared__ float  smd[NPART - 1][QB][3];    // partner-part candidate mins
    __shared__ int    smi[NPART - 1][QB][3];    // partner-part candidate gids
    __shared__ float  swgt[QB][3];
    __shared__ int    sidx[QB][3];

    const int tile = blockIdx.x;   // 0..511 (64 tiles per batch)
    const int b    = tile >> 6;
    const int n0   = (tile & 63) * QB;
    const int tid  = threadIdx.x;

    // --- stage xyz2[b] into shared with precomputed |p|^2 ---
    const float* x2b = xyz2 + (size_t)b * 3 * SS;
    #pragma unroll
    for (int s = tid; s < SS; s += TPB) {
        const float x = x2b[s], y = x2b[SS + s], z = x2b[2 * SS + s];
        sxyz[s] = make_float4(x, y, z, fmaf(x, x, fmaf(y, y, z * z)));
    }
    __syncthreads();

    // --- phase 1: candidate scan. Track top-3 GROUP MINS (value, group start).
    //     t = |p|^2 - 2 q.p orders identically to true squared distance. ---
    const int q    = tid & (QB - 1);
    const int part = tid >> 7;      // 0 or 1 (warp-uniform)
    const int n    = n0 + q;
    const float* x1b = xyz1 + (size_t)b * 3 * NN;
    const float qx = x1b[n], qy = x1b[NN + n], qz = x1b[2 * NN + n];
    const float ax = -2.0f * qx, ay = -2.0f * qy, az = -2.0f * qz;
    const float qq = fmaf(qx, qx, fmaf(qy, qy, qz * qz));

    float g0 = CUDART_MAX_NORMAL_F, g1 = CUDART_MAX_NORMAL_F, g2 = CUDART_MAX_NORMAL_F;
    int   c0 = 0, c1 = 0, c2 = 0;

    const int sbeg = part * SPT;
    for (int s = sbeg; s < sbeg + SPT; s += GSZ) {
        float t[GSZ];
        #pragma unroll
        for (int j = 0; j < GSZ; ++j) {
            const float4 p = sxyz[s + j];
            t[j] = fmaf(p.x, ax, fmaf(p.y, ay, fmaf(p.z, az, p.w)));
        }
        const float m01 = fminf(t[0], t[1]);
        const float m23 = fminf(t[2], t[3]);
        const float m45 = fminf(t[4], t[5]);
        const float m67 = fminf(t[6], t[7]);
        const float m   = fminf(fminf(m01, m23), fminf(m45, m67));
        BINS(m, s, g0, g1, g2, c0, c1, c2);   // branchless, always
    }

    // --- publish part-1 candidates; part 0 merges, rescans, writes weights ---
    if (part) {
        smd[part - 1][q][0] = g0; smd[part - 1][q][1] = g1; smd[part - 1][q][2] = g2;
        smi[part - 1][q][0] = c0; smi[part - 1][q][1] = c1; smi[part - 1][q][2] = c2;
    }
    __syncthreads();
    if (!part) {
        // merge partner candidate triples (part order preserves tie priority)
        #pragma unroll
        for (int p = 0; p < NPART - 1; ++p) {
            #pragma unroll
            for (int k = 0; k < 3; ++k) {
                const float tm = smd[p][q][k];
                const int   cm = smi[p][q][k];
                INS(tm, cm, g0, g1, g2, c0, c1, c2)
            }
        }
        // sort the 3 candidate groups by start index (ascending) so the exact
        // rescan visits points in index order (first-occurrence tie rule).
        int ga = c0, gb = c1, gc = c2, tmp;
        if (gb < ga) { tmp = ga; ga = gb; gb = tmp; }
        if (gc < gb) { tmp = gb; gb = gc; gc = tmp; }
        if (gb < ga) { tmp = ga; ga = gb; gb = tmp; }
        // duplicates impossible: each group id tracked at most once

        // exact top-3 over the <=24 candidate points
        float d0 = CUDART_MAX_NORMAL_F, d1 = CUDART_MAX_NORMAL_F, d2 = CUDART_MAX_NORMAL_F;
        int   i0 = 0, i1 = 0, i2 = 0;
        const int gs[3] = { ga, gb, gc };
        #pragma unroll
        for (int gk = 0; gk < 3; ++gk) {
            const int base = gs[gk];
            #pragma unroll
            for (int j = 0; j < GSZ; ++j) {
                const float4 p = sxyz[base + j];
                const float tt = fmaf(p.x, ax, fmaf(p.y, ay, fmaf(p.z, az, p.w)));
                INS(tt, base + j, d0, d1, d2, i0, i1, i2)
            }
        }

        // true squared distances and inverse-distance weights
        const float r0 = 1.0f / ((d0 + qq) + EPSF);
        const float r1 = 1.0f / ((d1 + qq) + EPSF);
        const float r2 = 1.0f / ((d2 + qq) + EPSF);
        const float inv = 1.0f / (r0 + r1 + r2);
        sidx[q][0] = i0; sidx[q][1] = i1; sidx[q][2] = i2;
        swgt[q][0] = r0 * inv; swgt[q][1] = r1 * inv; swgt[q][2] = r2 * inv;
    }
    __syncthreads();

    // --- phase 2: cooperative gather + weighted sum, coalesced float4 ---
    const int warp = tid >> 5;      // 0..7
    const int lane = tid & 31;
    const float4* p2f = (const float4*)(points2 + (size_t)b * SS * DD); // rows of 64 float4
    float4* ob = (float4*)(out + ((size_t)b * NN + n0) * DD);

    #pragma unroll
    for (int qi = warp; qi < QB; qi += TPB / 32) {
        const int j0 = sidx[qi][0] * (DD / 4);
        const int j1 = sidx[qi][1] * (DD / 4);
        const int j2 = sidx[qi][2] * (DD / 4);
        const float w0 = swgt[qi][0];
        const float w1 = swgt[qi][1];
        const float w2 = swgt[qi][2];
        float4* oq = ob + (size_t)qi * (DD / 4);
        #pragma unroll
        for (int j = lane; j < DD / 4; j += 32) {
            const float4 a = p2f[j0 + j];
            const float4 c = p2f[j1 + j];
            const float4 e = p2f[j2 + j];
            float4 r;
            r.x = w0 * a.x + w1 * c.x + w2 * e.x;
            r.y = w0 * a.y + w1 * c.y + w2 * e.y;
            r.z = w0 * a.z + w1 * c.z + w2 * e.z;
            r.w = w0 * a.w + w1 * c.w + w2 * e.w;
            oq[j] = r;
        }
    }
}

extern "C" void kernel_launch(void* const* d_in, const int* in_sizes, int n_in,
                              void* d_out, int out_size)
{
    // inputs: xyz1 [B,3,N], xyz2 [B,3,S], points1 [B,D,N] (unused), points2 [B,S,D]
    const float* xyz1    = (const float*)d_in[0];
    const float* xyz2    = (const float*)d_in[1];
    const float* points2 = (const float*)d_in[3];
    float* out = (float*)d_out;

    const int blocks = BB * (NN / QB);   // 8 * 64 = 512
    fp_interp_kernel<<<blocks, TPB>>>(xyz1, xyz2, points2, out);
}